// round 15
// baseline (speedup 1.0000x reference)
#include <cuda_runtime.h>

// SimpleNMS fused kernel, v4 — v3 + 5 CTAs/SM (reg-capped) + 6-op horizontal max.
// scores: (16, 1024, 1024, 1) fp32 -> out, same shape.
//
// One CTA stages 128x58; output tile 112x48 (staged cols [8,120), rows [5,53)).
// Edge garbage (shuffle clamp at cols 0/127, uninit mask rows 0/57) propagates
// at most 1 px per pool stage -> reaches only cols<=4/>=123, rows<=4/>=53,
// all outside the output window. So no column masks or row clamps are needed.
//
// Pipeline:  S1: m0 -> M0          (sync)
//            S23: sm1 in regs (halo-redundant), m1 -> M2   (sync)
//            S45: sm2 in regs, nm2, m2 -> global stores
//
// smem: float sc[58][128] + u32 M0[58][32] + u32 M2[58][32] = 44,544 B
//       x5 CTAs = 222.7 KB <= 228 KB carveout -> 5 CTAs/SM (regs capped 51).

#define IMG     1024
#define SROWS   58
#define SCOLS   128
#define SCOLW   32
#define TILE_X  112
#define TILE_Y  48
#define NT      256

struct SM {
    float    sc[SROWS][SCOLS];   // staged scores (-inf padded)
    unsigned M0[SROWS][SCOLW];   // m0 mask (0xFF/0x00 bytes, 4 px/u32)
    unsigned M2[SROWS][SCOLW];   // m1 mask
};

// Horizontal 3-max of a 6-wide window with shared pair maxes: 6 FMNMX (not 8).
__device__ __forceinline__ void hmax6(float vl, const float4& v, float vr,
                                      float4& hm) {
    float t01 = fmaxf(v.x, v.y);
    float t23 = fmaxf(v.z, v.w);
    hm.x = fmaxf(vl, t01);       // max(vl, x, y)
    hm.y = fmaxf(t01, v.z);      // max(x, y, z)
    hm.z = fmaxf(v.y, t23);      // max(y, z, w)
    hm.w = fmaxf(t23, vr);       // max(z, w, vr)
}

__device__ __forceinline__ float fmax3(float a, float b, float c) {
    return fmaxf(a, fmaxf(b, c));
}

// 0xFFFFFFFF / 0 full-width equality (FSET; fma-pipe, offloads ALU).
__device__ __forceinline__ unsigned fset_eq(float a, float b) {
    unsigned r;
    asm("set.eq.u32.f32 %0, %1, %2;" : "=r"(r) : "f"(a), "f"(b));
    return r;
}

// Pack 4 eq results into one word with 0xFF/0x00 bytes (3 PRMT).
__device__ __forceinline__ unsigned pack_eq4(const float4& c, float p0, float p1,
                                             float p2, float p3) {
    unsigned e0 = fset_eq(c.x, p0);
    unsigned e1 = fset_eq(c.y, p1);
    unsigned e2 = fset_eq(c.z, p2);
    unsigned e3 = fset_eq(c.w, p3);
    unsigned t0 = __byte_perm(e0, e1, 0x0040);
    unsigned t1 = __byte_perm(e2, e3, 0x0040);
    return __byte_perm(t0, t1, 0x5410);
}

// Score row: float4 + horizontal 3-max (neighbor columns via shuffle).
__device__ __forceinline__ void load_frow(const float (*buf)[SCOLS], int r, int cg,
                                          float4& hm, float4& v) {
    v = *reinterpret_cast<const float4*>(&buf[r][4 * cg]);
    float vl = __shfl_up_sync(0xffffffffu, v.w, 1);
    float vr = __shfl_down_sync(0xffffffffu, v.x, 1);
    hmax6(vl, v, vr, hm);
}

// Packed-mask row -> horizontal 3-OR word; also returns the center word.
__device__ __forceinline__ unsigned load_mrow2(const unsigned (*buf)[SCOLW], int r,
                                               unsigned cg, unsigned& center) {
    unsigned wv = buf[r][cg];
    center = wv;
    unsigned l  = __shfl_up_sync(0xffffffffu, wv, 1);
    unsigned rt = __shfl_down_sync(0xffffffffu, wv, 1);
    return wv | __funnelshift_l(l, wv, 8) | __funnelshift_r(wv, rt, 8);
}

// Suppressed-score row from a REGISTER mask word m:
// ss_j = v_j & ~splat(m byte j); horizontal 3-max via 2 shuffles.
__device__ __forceinline__ void load_ssrow(const float (*sc)[SCOLS], int r, int cg,
                                           unsigned m,
                                           float4& hm, float4& ss, float4& v) {
    v = *reinterpret_cast<const float4*>(&sc[r][4 * cg]);
    float s0 = __uint_as_float(__float_as_uint(v.x) & ~__byte_perm(m, 0, 0x0000));
    float s1 = __uint_as_float(__float_as_uint(v.y) & ~__byte_perm(m, 0, 0x1111));
    float s2 = __uint_as_float(__float_as_uint(v.z) & ~__byte_perm(m, 0, 0x2222));
    float s3 = __uint_as_float(__float_as_uint(v.w) & ~__byte_perm(m, 0, 0x3333));
    float sl = __shfl_up_sync(0xffffffffu, s3, 1);
    float sr = __shfl_down_sync(0xffffffffu, s0, 1);
    ss = make_float4(s0, s1, s2, s3);
    hmax6(sl, ss, sr, hm);
}

__global__ __launch_bounds__(NT, 5)
void nms_kernel(const float* __restrict__ in, float* __restrict__ out)
{
    extern __shared__ unsigned char raw[];
    SM* sm = reinterpret_cast<SM*>(raw);

    const int tid = threadIdx.x;
    const int w   = tid >> 5;
    const int cg  = tid & 31;
    const int bx = blockIdx.x, by = blockIdx.y, bz = blockIdx.z;
    const float* img  = in  + (size_t)bz * IMG * IMG;
    float*       oimg = out + (size_t)bz * IMG * IMG;
    const int gx0 = bx * TILE_X - 8;     // staged col 0 (16B aligned)
    const int gy0 = by * TILE_Y - 5;     // staged row 0
    const float NEG = -__int_as_float(0x7f800000);

    // ---- Stage 0: load staged scores (-inf outside image) ----------------
    {
        const bool interior = (bx >= 1) && (bx <= 8) && (by >= 1) && (by <= 20);
        const int c0 = 4 * cg;
        if (interior) {
            #pragma unroll
            for (int k = 0; k < 8; k++) {
                int r = w + 8 * k;
                if (r >= SROWS) break;
                const float4 v = *reinterpret_cast<const float4*>(
                    img + (size_t)(gy0 + r) * IMG + gx0 + c0);
                *reinterpret_cast<float4*>(&sm->sc[r][c0]) = v;
            }
        } else {
            #pragma unroll
            for (int k = 0; k < 8; k++) {
                int r = w + 8 * k;
                if (r >= SROWS) break;
                int gy = gy0 + r;
                bool yok = (unsigned)gy < IMG;
                const float* rp = img + (size_t)gy * IMG;
                int gx = gx0 + c0;
                float4 v;
                v.x = (yok && (unsigned)(gx + 0) < IMG) ? rp[gx + 0] : NEG;
                v.y = (yok && (unsigned)(gx + 1) < IMG) ? rp[gx + 1] : NEG;
                v.z = (yok && (unsigned)(gx + 2) < IMG) ? rp[gx + 2] : NEG;
                v.w = (yok && (unsigned)(gx + 3) < IMG) ? rp[gx + 3] : NEG;
                *reinterpret_cast<float4*>(&sm->sc[r][c0]) = v;
            }
        }
    }
    __syncthreads();

    // ---- S1: m0 = (s == pool3(s)) -> M0, rows [1+7w, 8+7w), no masks -----
    {
        const int r0 = 1 + 7 * w;
        float4 hmA, hmB, hmC, vB, vC, t;
        load_frow(sm->sc, r0 - 1, cg, hmA, t);
        load_frow(sm->sc, r0,     cg, hmB, vB);
        #pragma unroll
        for (int k = 0; k < 7; k++) {
            int r = r0 + k;
            load_frow(sm->sc, r + 1, cg, hmC, vC);
            float p0 = fmax3(hmA.x, hmB.x, hmC.x);
            float p1 = fmax3(hmA.y, hmB.y, hmC.y);
            float p2 = fmax3(hmA.z, hmB.z, hmC.z);
            float p3 = fmax3(hmA.w, hmB.w, hmC.w);
            sm->M0[r][cg] = pack_eq4(vB, p0, p1, p2, p3);
            hmA = hmB; hmB = hmC; vB = vC;
        }
    }
    __syncthreads();

    // ---- S23: sm1 in regs; m1 = m0 | (nm1 & ~sm1) -> M2, rows [1+7w,8+7w)
    {
        const int r0 = 1 + 7 * w;
        unsigned c_t, cA, cB, cC;
        unsigned hq0 = load_mrow2(sm->M0, max(r0 - 2, 0), cg, c_t);
        unsigned hq1 = load_mrow2(sm->M0, r0 - 1, cg, c_t);
        unsigned hq2 = load_mrow2(sm->M0, r0,     cg, cA);
        unsigned sm1_prev = hq0 | hq1 | hq2;            // sm1 @ r0-1
        float4 hmA, hmB, hmC, ssB, ssC, sT, vT;
        load_ssrow(sm->sc, r0 - 1, cg, sm1_prev, hmA, sT, vT);
        unsigned hq3 = load_mrow2(sm->M0, r0 + 1, cg, cB);
        unsigned sm1_cur = hq1 | hq2 | hq3;             // sm1 @ r0
        load_ssrow(sm->sc, r0, cg, sm1_cur, hmB, ssB, vT);
        unsigned hq_r = hq2, hq_r1 = hq3;
        #pragma unroll
        for (int k = 0; k < 7; k++) {
            int r = r0 + k;
            unsigned hq_r2 = load_mrow2(sm->M0, min(r + 2, SROWS - 1), cg, cC);
            unsigned sm1_next = hq_r | hq_r1 | hq_r2;   // sm1 @ r+1
            load_ssrow(sm->sc, r + 1, cg, sm1_next, hmC, ssC, vT);
            float p0 = fmax3(hmA.x, hmB.x, hmC.x);
            float p1 = fmax3(hmA.y, hmB.y, hmC.y);
            float p2 = fmax3(hmA.z, hmB.z, hmC.z);
            float p3 = fmax3(hmA.w, hmB.w, hmC.w);
            unsigned nm = pack_eq4(ssB, p0, p1, p2, p3);
            sm->M2[r][cg] = cA | (nm & ~sm1_cur);       // m1 = m0 | (nm1 & ~sm1)
            hmA = hmB; hmB = hmC; ssB = ssC;
            sm1_cur = sm1_next; hq_r = hq_r1; hq_r1 = hq_r2;
            cA = cB; cB = cC;
        }
    }
    __syncthreads();

    // ---- S45: sm2 in regs; m2 = m1 | (nm2 & ~sm2); out, rows [5+6w,11+6w)
    {
        const int r0 = 5 + 6 * w;
        unsigned c_t, cA, cB, cC;
        unsigned hq0 = load_mrow2(sm->M2, r0 - 2, cg, c_t);
        unsigned hq1 = load_mrow2(sm->M2, r0 - 1, cg, c_t);
        unsigned hq2 = load_mrow2(sm->M2, r0,     cg, cA);
        unsigned sm2_prev = hq0 | hq1 | hq2;            // sm2 @ r0-1
        float4 hmA, hmB, hmC, ssB, ssC, sT, vT, vB, vC;
        load_ssrow(sm->sc, r0 - 1, cg, sm2_prev, hmA, sT, vT);
        unsigned hq3 = load_mrow2(sm->M2, r0 + 1, cg, cB);
        unsigned sm2_cur = hq1 | hq2 | hq3;             // sm2 @ r0
        load_ssrow(sm->sc, r0, cg, sm2_cur, hmB, ssB, vB);
        unsigned hq_r = hq2, hq_r1 = hq3;
        const int c0 = 4 * cg;
        const int gxo = gx0 + c0;
        const bool x_ok = (cg >= 2) && (cg < 30) && ((unsigned)gxo < IMG);
        #pragma unroll
        for (int k = 0; k < 6; k++) {
            int r = r0 + k;
            unsigned hq_r2 = load_mrow2(sm->M2, r + 2, cg, cC);
            unsigned sm2_next = hq_r | hq_r1 | hq_r2;   // sm2 @ r+1
            load_ssrow(sm->sc, r + 1, cg, sm2_next, hmC, ssC, vC);
            float p0 = fmax3(hmA.x, hmB.x, hmC.x);
            float p1 = fmax3(hmA.y, hmB.y, hmC.y);
            float p2 = fmax3(hmA.z, hmB.z, hmC.z);
            float p3 = fmax3(hmA.w, hmB.w, hmC.w);
            unsigned nm = pack_eq4(ssB, p0, p1, p2, p3);
            unsigned m2 = cA | (nm & ~sm2_cur);         // m2 = m1 | (nm2 & ~sm2)
            int gy = gy0 + r;
            if (x_ok && (unsigned)gy < IMG) {
                float4 o;
                o.x = __uint_as_float(__float_as_uint(vB.x) & __byte_perm(m2, 0, 0x0000));
                o.y = __uint_as_float(__float_as_uint(vB.y) & __byte_perm(m2, 0, 0x1111));
                o.z = __uint_as_float(__float_as_uint(vB.z) & __byte_perm(m2, 0, 0x2222));
                o.w = __uint_as_float(__float_as_uint(vB.w) & __byte_perm(m2, 0, 0x3333));
                *reinterpret_cast<float4*>(oimg + (size_t)gy * IMG + gxo) = o;
            }
            hmA = hmB; hmB = hmC; ssB = ssC; vB = vC;
            sm2_cur = sm2_next; hq_r = hq_r1; hq_r1 = hq_r2;
            cA = cB; cB = cC;
        }
    }
}

extern "C" void kernel_launch(void* const* d_in, const int* in_sizes, int n_in,
                              void* d_out, int out_size)
{
    const float* scores = (const float*)d_in[0];
    float* out = (float*)d_out;

    const size_t smem = sizeof(SM);   // 44,544 B
    cudaFuncSetAttribute(nms_kernel,
                         cudaFuncAttributeMaxDynamicSharedMemorySize,
                         (int)smem);

    dim3 grid((IMG + TILE_X - 1) / TILE_X,   // 10
              (IMG + TILE_Y - 1) / TILE_Y,   // 22
              16);
    nms_kernel<<<grid, NT, smem>>>(scores, out);
}